// round 1
// baseline (speedup 1.0000x reference)
#include <cuda_runtime.h>

#define BATCH 512
#define INC   1152
#define IND   8
#define NC    10
#define DC    16
#define JD    160     // NC*DC
#define JD4   40      // JD/4
#define EPSQ  1e-7f

// Scratch for u_hat, layout [b][i][f] with f indexing float4s over (j*16+d).
// 512*1152*40 float4 = 377 MB. Static __device__ global (no runtime alloc).
__device__ float4 g_uhat[(size_t)BATCH * INC * JD4];

// ---------------------------------------------------------------------------
// Kernel A: u_hat[b,i,j,d] = sum_k inputs[b,i,k] * W[j,i,d,k]
// One warp per (i, batch-chunk). Lane holds 5 W rows (idx = 32*o + lane) in
// registers, loops over 64 batches. Stores are 128B-coalesced per o.
// ---------------------------------------------------------------------------
#define NBCH 8
#define BCH  (BATCH / NBCH)   // 64

__global__ __launch_bounds__(256) void uhat_kernel(const float* __restrict__ inp,
                                                   const float* __restrict__ W) {
    const int warp = threadIdx.x >> 5;
    const int lane = threadIdx.x & 31;
    const int gw = blockIdx.x * 8 + warp;      // [0, INC*NBCH)
    const int i = gw >> 3;                     // NBCH == 8
    const int chunk = gw & 7;

    // Load 5 W rows (8 floats each) into registers
    float w[5][8];
#pragma unroll
    for (int o = 0; o < 5; o++) {
        const int idx = 32 * o + lane;
        const int j = idx >> 4;
        const int d = idx & 15;
        const float4* wp =
            (const float4*)(W + (((size_t)j * INC + i) * DC + d) * IND);
        float4 a = __ldg(wp);
        float4 c = __ldg(wp + 1);
        w[o][0] = a.x; w[o][1] = a.y; w[o][2] = a.z; w[o][3] = a.w;
        w[o][4] = c.x; w[o][5] = c.y; w[o][6] = c.z; w[o][7] = c.w;
    }

    const int b0 = chunk * BCH;
#pragma unroll 2
    for (int bb = 0; bb < BCH; bb++) {
        const int b = b0 + bb;
        const float4* ip = (const float4*)(inp + ((size_t)b * INC + i) * IND);
        float4 a = __ldg(ip);
        float4 c = __ldg(ip + 1);
        float in[8] = {a.x, a.y, a.z, a.w, c.x, c.y, c.z, c.w};
        float* up = (float*)(g_uhat + ((size_t)b * INC + i) * JD4);
#pragma unroll
        for (int o = 0; o < 5; o++) {
            float acc = 0.f;
#pragma unroll
            for (int k = 0; k < 8; k++) acc = fmaf(in[k], w[o][k], acc);
            up[32 * o + lane] = acc;
        }
    }
}

// ---------------------------------------------------------------------------
// Kernel R: dynamic routing, one CTA per batch, 3 fused passes over u_hat[b].
// b-logits are linear in V = sum of previous v's: t[j,i] = V . u_hat[j,i,:].
// Per i: 4-lane butterfly dot-reduce -> per-i softmax over j -> accumulate s.
// ---------------------------------------------------------------------------
#define RW 12   // warps per CTA (384 threads); 1152 / 12 = 96 iters/warp

__global__ __launch_bounds__(384) void route_kernel(float* __restrict__ out) {
    __shared__ float4 Vsm4[JD4];
    __shared__ float4 spart4[RW][JD4];
    __shared__ float sfin[JD];
    __shared__ float scale_sm[NC];

    const int tid = threadIdx.x;
    const int warp = tid >> 5;
    const int lane = tid & 31;
    const int b = blockIdx.x;
    const bool hasB = (lane < 8);

    const float4* ub_base = g_uhat + (size_t)b * INC * JD4;
    float* Vf = (float*)Vsm4;
    float* spf = (float*)spart4;

    for (int pass = 0; pass < 3; pass++) {
        float4 sa = make_float4(0.f, 0.f, 0.f, 0.f);
        float4 sb = make_float4(0.f, 0.f, 0.f, 0.f);

        if (pass == 0) {
            // c is exactly uniform (softmax of zeros) -> s = 0.1 * sum_i u_hat
#pragma unroll 2
            for (int i = warp; i < INC; i += RW) {
                const float4* up = ub_base + (size_t)i * JD4;
                float4 ua = up[lane];
                sa.x += ua.x; sa.y += ua.y; sa.z += ua.z; sa.w += ua.w;
                if (hasB) {
                    float4 ub = up[32 + lane];
                    sb.x += ub.x; sb.y += ub.y; sb.z += ub.z; sb.w += ub.w;
                }
            }
            sa.x *= 0.1f; sa.y *= 0.1f; sa.z *= 0.1f; sa.w *= 0.1f;
            sb.x *= 0.1f; sb.y *= 0.1f; sb.z *= 0.1f; sb.w *= 0.1f;
        } else {
            float4 Va = Vsm4[lane];
            float4 Vb = make_float4(0.f, 0.f, 0.f, 0.f);
            if (hasB) Vb = Vsm4[32 + lane];
#pragma unroll 2
            for (int i = warp; i < INC; i += RW) {
                const float4* up = ub_base + (size_t)i * JD4;
                float4 ua = up[lane];
                float4 ub = make_float4(0.f, 0.f, 0.f, 0.f);
                if (hasB) ub = up[32 + lane];

                // partial dots: lane covers 4 d's of one j
                float ta = ua.x * Va.x + ua.y * Va.y + ua.z * Va.z + ua.w * Va.w;
                float tb = ub.x * Vb.x + ub.y * Vb.y + ub.z * Vb.z + ub.w * Vb.w;
                // reduce across 4-lane group -> t[j] replicated in its group
                ta += __shfl_xor_sync(0xffffffffu, ta, 1);
                ta += __shfl_xor_sync(0xffffffffu, ta, 2);
                tb += __shfl_xor_sync(0xffffffffu, tb, 1);
                tb += __shfl_xor_sync(0xffffffffu, tb, 2);
                if (!hasB) tb = -1e30f;  // mask invalid lanes out of max/exp

                // global max over the 10 logits
                float m = fmaxf(ta, tb);
                m = fmaxf(m, __shfl_xor_sync(0xffffffffu, m, 4));
                m = fmaxf(m, __shfl_xor_sync(0xffffffffu, m, 8));
                m = fmaxf(m, __shfl_xor_sync(0xffffffffu, m, 16));

                float ea = __expf(ta - m);
                float eb = __expf(tb - m);  // == 0 for !hasB lanes

                // sum over lanes counts each j 4x -> divide by 4 via (4/sv)
                float sv = ea + eb;
                sv += __shfl_xor_sync(0xffffffffu, sv, 1);
                sv += __shfl_xor_sync(0xffffffffu, sv, 2);
                sv += __shfl_xor_sync(0xffffffffu, sv, 4);
                sv += __shfl_xor_sync(0xffffffffu, sv, 8);
                sv += __shfl_xor_sync(0xffffffffu, sv, 16);
                float inv = __fdividef(4.0f, sv);
                float ca = ea * inv;
                float cb = eb * inv;

                sa.x = fmaf(ca, ua.x, sa.x);
                sa.y = fmaf(ca, ua.y, sa.y);
                sa.z = fmaf(ca, ua.z, sa.z);
                sa.w = fmaf(ca, ua.w, sa.w);
                sb.x = fmaf(cb, ub.x, sb.x);
                sb.y = fmaf(cb, ub.y, sb.y);
                sb.z = fmaf(cb, ub.z, sb.z);
                sb.w = fmaf(cb, ub.w, sb.w);
            }
        }

        // per-warp partials -> smem
        spart4[warp][lane] = sa;
        if (hasB) spart4[warp][32 + lane] = sb;
        __syncthreads();

        // cross-warp reduce
        if (tid < JD) {
            float s = 0.f;
#pragma unroll
            for (int w2 = 0; w2 < RW; w2++) s += spf[w2 * JD + tid];
            sfin[tid] = s;
        }
        __syncthreads();

        // squash scale per output capsule j
        if (tid < NC) {
            float sq = 0.f;
#pragma unroll
            for (int d = 0; d < DC; d++) {
                float v = sfin[tid * DC + d];
                sq = fmaf(v, v, sq);
            }
            scale_sm[tid] = sq / ((1.0f + sq) * sqrtf(sq + EPSQ));
        }
        __syncthreads();

        if (tid < JD) {
            float v = scale_sm[tid >> 4] * sfin[tid];
            if (pass == 2)
                out[(size_t)b * JD + tid] = v;
            else
                Vf[tid] = (pass == 0) ? v : (Vf[tid] + v);
        }
        __syncthreads();  // Vsm ready for next pass; spart safe to overwrite
    }
}

// ---------------------------------------------------------------------------
extern "C" void kernel_launch(void* const* d_in, const int* in_sizes, int n_in,
                              void* d_out, int out_size) {
    const float* inputs = (const float*)d_in[0];  // [512, 1152, 8]
    const float* W      = (const float*)d_in[1];  // [10, 1152, 16, 8]
    float* out          = (float*)d_out;          // [512, 10, 16]

    uhat_kernel<<<(INC * NBCH) / 8, 256>>>(inputs, W);
    route_kernel<<<BATCH, 384>>>(out);
}

// round 3
// speedup vs baseline: 1.0176x; 1.0176x over previous
#include <cuda_runtime.h>
#include <cuda_fp16.h>
#include <cstdint>

#define BATCH 512
#define INC   1152
#define NC    10
#define DC    16
#define JD    160      // NC*DC
#define NSLOT 80       // half2 slots per (b,i): slot m holds jd {2m, 2m+1}
#define IHALF 576      // i-range per route CTA (cluster of 2 per batch)
#define RW    12       // warps per route CTA
#define EPSQ  1e-7f

// u_hat in fp16, layout [b][i][slot], slot m = jd pair (2m, 2m+1). 188 MB.
__device__ __half2 g_uhat[(size_t)BATCH * INC * NSLOT];

// ---------------------------------------------------------------------------
// helpers
// ---------------------------------------------------------------------------
__device__ __forceinline__ void cluster_sync() {
    asm volatile("barrier.cluster.arrive.aligned;\n\t"
                 "barrier.cluster.wait.aligned;" ::: "memory");
}

__device__ __forceinline__ float peer_f32(const float* p, unsigned int peer) {
    unsigned int a = (unsigned int)__cvta_generic_to_shared(p);
    unsigned int r;
    asm("mapa.shared::cluster.u32 %0, %1, %2;" : "=r"(r) : "r"(a), "r"(peer));
    float v;
    asm volatile("ld.shared::cluster.f32 %0, [%1];" : "=f"(v) : "r"(r));
    return v;
}

// ---------------------------------------------------------------------------
// Kernel A: u_hat[b,i,jd] = sum_k inputs[b,i,k] * W[jd(i),k], fp16 output.
// Warp owns (i, 64-batch chunk). Lane owns jd pairs {2l,2l+1},{64+2l,..},
// {128+2l,..(l<16)} -> half2 slots l, 32+l, 64+l. W held in registers.
// ---------------------------------------------------------------------------
__global__ __launch_bounds__(256) void uhat_kernel(const float* __restrict__ inp,
                                                   const float* __restrict__ W) {
    const int warp = threadIdx.x >> 5;
    const int lane = threadIdx.x & 31;
    const int gw = blockIdx.x * 8 + warp;   // [0, 9216)
    const int i = gw >> 3;
    const int chunk = gw & 7;

    float wA[16], wB[16], wC[16];
#define LOADW(dst, jd0)                                                        \
    {                                                                          \
        const int j_ = (jd0) >> 4, d_ = (jd0) & 15;                            \
        const float4* p_ =                                                     \
            (const float4*)(W + (((size_t)j_ * INC + i) * DC + d_) * 8);       \
        float4 q0 = __ldg(p_), q1 = __ldg(p_ + 1), q2 = __ldg(p_ + 2),         \
               q3 = __ldg(p_ + 3);                                             \
        dst[0] = q0.x;  dst[1] = q0.y;  dst[2] = q0.z;  dst[3] = q0.w;         \
        dst[4] = q1.x;  dst[5] = q1.y;  dst[6] = q1.z;  dst[7] = q1.w;         \
        dst[8] = q2.x;  dst[9] = q2.y;  dst[10] = q2.z; dst[11] = q2.w;        \
        dst[12] = q3.x; dst[13] = q3.y; dst[14] = q3.z; dst[15] = q3.w;        \
    }
    LOADW(wA, 2 * lane);
    LOADW(wB, 64 + 2 * lane);
    if (lane < 16) {
        LOADW(wC, 128 + 2 * lane);
    } else {
#pragma unroll
        for (int k = 0; k < 16; k++) wC[k] = 0.f;
    }
#undef LOADW

    const int b0 = chunk * 64;
#pragma unroll 2
    for (int bb = 0; bb < 64; bb++) {
        const int b = b0 + bb;
        const float4* ip = (const float4*)(inp + ((size_t)b * INC + i) * 8);
        float4 x = __ldg(ip), y = __ldg(ip + 1);
        float in[8] = {x.x, x.y, x.z, x.w, y.x, y.y, y.z, y.w};

        float aA0 = 0.f, aA1 = 0.f, aB0 = 0.f, aB1 = 0.f, aC0 = 0.f, aC1 = 0.f;
#pragma unroll
        for (int k = 0; k < 8; k++) {
            aA0 = fmaf(in[k], wA[k], aA0);
            aA1 = fmaf(in[k], wA[8 + k], aA1);
            aB0 = fmaf(in[k], wB[k], aB0);
            aB1 = fmaf(in[k], wB[8 + k], aB1);
            aC0 = fmaf(in[k], wC[k], aC0);
            aC1 = fmaf(in[k], wC[8 + k], aC1);
        }
        __half2* up = g_uhat + ((size_t)b * INC + i) * NSLOT;
        up[lane] = __floats2half2_rn(aA0, aA1);
        up[32 + lane] = __floats2half2_rn(aB0, aB1);
        if (lane < 16) up[64 + lane] = __floats2half2_rn(aC0, aC1);
    }
}

// ---------------------------------------------------------------------------
// Kernel R: routing. Cluster of 2 CTAs per batch; each CTA caches its 576-i
// half of u_hat[b] in smem (184 KB fp16) while accumulating pass-0's uniform
// sum, then runs passes 1,2 from smem. 160-float cross-CTA reduces via DSMEM.
// Lane layout: lanes 0..19 active, lane l owns half2 slots 4l..4l+3 (16B),
// all within j = l>>1; pair-shuffle(xor 1) completes the d-dot.
// ---------------------------------------------------------------------------
__global__ __launch_bounds__(384, 1) __cluster_dims__(2, 1, 1)
void route_kernel(float* __restrict__ out) {
    extern __shared__ char smraw[];
    __half2* Usm = (__half2*)smraw;                        // IHALF*80 half2
    float* red = (float*)(smraw + (size_t)IHALF * NSLOT * 4);  // RW*160
    float* sfin = red + RW * JD;                           // 160 (DSMEM-read)
    float* stot = sfin + JD;                               // 160
    float* Vsm = stot + JD;                                // 160
    float* scl = Vsm + JD;                                 // 16

    const int tid = threadIdx.x;
    const int warp = tid >> 5;
    const int lane = tid & 31;
    const int b = blockIdx.x >> 1;
    const unsigned int rank = blockIdx.x & 1, peer = rank ^ 1;
    const bool act = (lane < 20);
    const int sl = act ? 4 * lane : 0;
    float2* red2 = (float2*)red;

    const __half2* gsrc = g_uhat + ((size_t)b * INC + rank * IHALF) * NSLOT;

    // ---- stream u_hat half -> smem, accumulate pass-0 (c = 0.1 uniform) ----
    float2 a0 = make_float2(0.f, 0.f), a1 = a0, a2 = a0, a3 = a0;
    if (act) {
#pragma unroll 2
        for (int i = warp; i < IHALF; i += RW) {
            uint4 u = *(const uint4*)(gsrc + (size_t)i * NSLOT + sl);
            *(uint4*)(Usm + (size_t)i * NSLOT + sl) = u;
            __half2 h0 = *(__half2*)&u.x, h1 = *(__half2*)&u.y;
            __half2 h2 = *(__half2*)&u.z, h3 = *(__half2*)&u.w;
            float2 f0 = __half22float2(h0), f1 = __half22float2(h1);
            float2 f2 = __half22float2(h2), f3 = __half22float2(h3);
            a0.x += f0.x; a0.y += f0.y; a1.x += f1.x; a1.y += f1.y;
            a2.x += f2.x; a2.y += f2.y; a3.x += f3.x; a3.y += f3.y;
        }
        red2[warp * 80 + sl + 0] = a0;
        red2[warp * 80 + sl + 1] = a1;
        red2[warp * 80 + sl + 2] = a2;
        red2[warp * 80 + sl + 3] = a3;
    }
    __syncthreads();
    if (tid < JD) {
        float s = 0.f;
#pragma unroll
        for (int w = 0; w < RW; w++) s += red[w * JD + tid];
        sfin[tid] = s;
    }
    __syncthreads();
    cluster_sync();
    if (tid < JD) stot[tid] = 0.1f * (sfin[tid] + peer_f32(sfin + tid, peer));
    __syncthreads();
    if (tid < NC) {
        float sq = 0.f;
#pragma unroll
        for (int d = 0; d < DC; d++) {
            float v = stot[tid * DC + d];
            sq = fmaf(v, v, sq);
        }
        scl[tid] = sq / ((1.0f + sq) * sqrtf(sq + EPSQ));
    }
    __syncthreads();
    if (tid < JD) Vsm[tid] = scl[tid >> 4] * stot[tid];
    __syncthreads();
    cluster_sync();  // peer done reading sfin; Vsm ready

    // ---- passes 1,2 from smem ----
    for (int p = 1; p <= 2; p++) {
        const float2* V2 = (const float2*)Vsm;
        float2 v0 = V2[sl], v1 = V2[sl + 1], v2 = V2[sl + 2], v3 = V2[sl + 3];
        float2 s0 = make_float2(0.f, 0.f), s1 = s0, s2 = s0, s3 = s0;
#pragma unroll 2
        for (int i = warp; i < IHALF; i += RW) {
            uint4 u = *(const uint4*)(Usm + (size_t)i * NSLOT + sl);
            __half2 h0 = *(__half2*)&u.x, h1 = *(__half2*)&u.y;
            __half2 h2 = *(__half2*)&u.z, h3 = *(__half2*)&u.w;
            float2 f0 = __half22float2(h0), f1 = __half22float2(h1);
            float2 f2 = __half22float2(h2), f3 = __half22float2(h3);

            float t = f0.x * v0.x + f0.y * v0.y;
            t = fmaf(f1.x, v1.x, t); t = fmaf(f1.y, v1.y, t);
            t = fmaf(f2.x, v2.x, t); t = fmaf(f2.y, v2.y, t);
            t = fmaf(f3.x, v3.x, t); t = fmaf(f3.y, v3.y, t);
            t += __shfl_xor_sync(0xffffffffu, t, 1);  // full dot for j = lane>>1

            // |t| < ~4 -> no max-subtraction needed
            float e = act ? __expf(t) : 0.f;
            float sv = e;
            sv += __shfl_xor_sync(0xffffffffu, sv, 2);
            sv += __shfl_xor_sync(0xffffffffu, sv, 4);
            sv += __shfl_xor_sync(0xffffffffu, sv, 8);
            sv += __shfl_xor_sync(0xffffffffu, sv, 16);  // = sum_j e_j exactly
            float c = e * __fdividef(1.f, sv);

            s0.x = fmaf(c, f0.x, s0.x); s0.y = fmaf(c, f0.y, s0.y);
            s1.x = fmaf(c, f1.x, s1.x); s1.y = fmaf(c, f1.y, s1.y);
            s2.x = fmaf(c, f2.x, s2.x); s2.y = fmaf(c, f2.y, s2.y);
            s3.x = fmaf(c, f3.x, s3.x); s3.y = fmaf(c, f3.y, s3.y);
        }
        if (act) {
            red2[warp * 80 + sl + 0] = s0;
            red2[warp * 80 + sl + 1] = s1;
            red2[warp * 80 + sl + 2] = s2;
            red2[warp * 80 + sl + 3] = s3;
        }
        __syncthreads();
        if (tid < JD) {
            float s = 0.f;
#pragma unroll
            for (int w = 0; w < RW; w++) s += red[w * JD + tid];
            sfin[tid] = s;
        }
        __syncthreads();
        cluster_sync();
        if (tid < JD) stot[tid] = sfin[tid] + peer_f32(sfin + tid, peer);
        __syncthreads();
        if (tid < NC) {
            float sq = 0.f;
#pragma unroll
            for (int d = 0; d < DC; d++) {
                float v = stot[tid * DC + d];
                sq = fmaf(v, v, sq);
            }
            scl[tid] = sq / ((1.0f + sq) * sqrtf(sq + EPSQ));
        }
        __syncthreads();
        if (p == 1) {
            if (tid < JD) Vsm[tid] += scl[tid >> 4] * stot[tid];
            __syncthreads();
        } else {
            if (rank == 0 && tid < JD)
                out[(size_t)b * JD + tid] = scl[tid >> 4] * stot[tid];
        }
        cluster_sync();  // sfin reuse / exit safety
    }
}

// ---------------------------------------------------------------------------
extern "C" void kernel_launch(void* const* d_in, const int* in_sizes, int n_in,
                              void* d_out, int out_size) {
    const float* inputs = (const float*)d_in[0];  // [512, 1152, 8]
    const float* W = (const float*)d_in[1];       // [10, 1152, 16, 8]
    float* out = (float*)d_out;                   // [512, 10, 16]

    uhat_kernel<<<INC, 256>>>(inputs, W);

    const int smem = IHALF * NSLOT * 4 + (RW * JD + 3 * JD + 16) * 4;  // ~194 KB
    cudaFuncSetAttribute(route_kernel,
                         cudaFuncAttributeMaxDynamicSharedMemorySize, smem);
    route_kernel<<<BATCH * 2, 384, smem>>>(out);
}

// round 4
// speedup vs baseline: 1.2009x; 1.1801x over previous
#include <cuda_runtime.h>
#include <cuda_fp16.h>
#include <cstdint>

#define BATCH 512
#define INC   1152
#define NC    10
#define DC    16
#define JD    160      // NC*DC
#define NSLOT 80       // half2 slots per (b,i): slot m holds jd {2m, 2m+1}
#define CSZ   4        // cluster CTAs per batch
#define IQ    288      // i-range per route CTA (INC / CSZ)
#define RW    12       // warps per route CTA
#define EPSQ  1e-7f

// u_hat in fp16, layout [b][i][slot], slot m = jd pair (2m, 2m+1). 188 MB.
__device__ __half2 g_uhat[(size_t)BATCH * INC * NSLOT];

// ---------------------------------------------------------------------------
// helpers
// ---------------------------------------------------------------------------
__device__ __forceinline__ void cluster_sync() {
    asm volatile("barrier.cluster.arrive.aligned;\n\t"
                 "barrier.cluster.wait.aligned;" ::: "memory");
}

__device__ __forceinline__ float peer_f32(const float* p, unsigned int peer) {
    unsigned int a = (unsigned int)__cvta_generic_to_shared(p);
    unsigned int r;
    asm("mapa.shared::cluster.u32 %0, %1, %2;" : "=r"(r) : "r"(a), "r"(peer));
    float v;
    asm volatile("ld.shared::cluster.f32 %0, [%1];" : "=f"(v) : "r"(r));
    return v;
}

// ---------------------------------------------------------------------------
// Kernel A: u_hat[b,i,jd] = sum_k inputs[b,i,k] * W[jd(i),k], fp16 output.
// Warp owns (i, 64-batch chunk); W rows in registers; inputs prefetched one
// iteration ahead for MLP.
// ---------------------------------------------------------------------------
__global__ __launch_bounds__(256) void uhat_kernel(const float* __restrict__ inp,
                                                   const float* __restrict__ W) {
    const int warp = threadIdx.x >> 5;
    const int lane = threadIdx.x & 31;
    const int gw = blockIdx.x * 8 + warp;   // [0, 9216)
    const int i = gw >> 3;
    const int chunk = gw & 7;

    float wA[16], wB[16], wC[16];
#define LOADW(dst, jd0)                                                        \
    {                                                                          \
        const int j_ = (jd0) >> 4, d_ = (jd0) & 15;                            \
        const float4* p_ =                                                     \
            (const float4*)(W + (((size_t)j_ * INC + i) * DC + d_) * 8);       \
        float4 q0 = __ldg(p_), q1 = __ldg(p_ + 1), q2 = __ldg(p_ + 2),         \
               q3 = __ldg(p_ + 3);                                             \
        dst[0] = q0.x;  dst[1] = q0.y;  dst[2] = q0.z;  dst[3] = q0.w;         \
        dst[4] = q1.x;  dst[5] = q1.y;  dst[6] = q1.z;  dst[7] = q1.w;         \
        dst[8] = q2.x;  dst[9] = q2.y;  dst[10] = q2.z; dst[11] = q2.w;        \
        dst[12] = q3.x; dst[13] = q3.y; dst[14] = q3.z; dst[15] = q3.w;        \
    }
    LOADW(wA, 2 * lane);
    LOADW(wB, 64 + 2 * lane);
    if (lane < 16) {
        LOADW(wC, 128 + 2 * lane);
    } else {
#pragma unroll
        for (int k = 0; k < 16; k++) wC[k] = 0.f;
    }
#undef LOADW

    const int b0 = chunk * 64;
    const float4* ip0 = (const float4*)(inp + ((size_t)b0 * INC + i) * 8);
    float4 x = __ldg(ip0), y = __ldg(ip0 + 1);
#pragma unroll 2
    for (int bb = 0; bb < 64; bb++) {
        float in[8] = {x.x, x.y, x.z, x.w, y.x, y.y, y.z, y.w};
        if (bb + 1 < 64) {  // prefetch next batch's inputs
            const float4* ipn =
                (const float4*)(inp + ((size_t)(b0 + bb + 1) * INC + i) * 8);
            x = __ldg(ipn);
            y = __ldg(ipn + 1);
        }

        float aA0 = 0.f, aA1 = 0.f, aB0 = 0.f, aB1 = 0.f, aC0 = 0.f, aC1 = 0.f;
#pragma unroll
        for (int k = 0; k < 8; k++) {
            aA0 = fmaf(in[k], wA[k], aA0);
            aA1 = fmaf(in[k], wA[8 + k], aA1);
            aB0 = fmaf(in[k], wB[k], aB0);
            aB1 = fmaf(in[k], wB[8 + k], aB1);
            aC0 = fmaf(in[k], wC[k], aC0);
            aC1 = fmaf(in[k], wC[8 + k], aC1);
        }
        __half2* up = g_uhat + ((size_t)(b0 + bb) * INC + i) * NSLOT;
        up[lane] = __floats2half2_rn(aA0, aA1);
        up[32 + lane] = __floats2half2_rn(aB0, aB1);
        if (lane < 16) up[64 + lane] = __floats2half2_rn(aC0, aC1);
    }
}

// ---------------------------------------------------------------------------
// Kernel R: routing. Cluster of 4 CTAs per batch; each CTA caches its 288-i
// quarter of u_hat[b] in smem (92 KB fp16) while accumulating pass-0's uniform
// sum, then runs passes 1,2 from smem. ~102 KB smem -> 2 CTAs/SM (24 warps).
// Lane layout: lanes 0..19 active, lane l owns half2 slots 4l..4l+3 (16B),
// all within j = l>>1; pair-shuffle(xor 1) completes the d-dot.
// ---------------------------------------------------------------------------
__global__ __launch_bounds__(384) __cluster_dims__(CSZ, 1, 1)
void route_kernel(float* __restrict__ out) {
    extern __shared__ char smraw[];
    __half2* Usm = (__half2*)smraw;                            // IQ*80 half2
    float* red = (float*)(smraw + (size_t)IQ * NSLOT * 4);     // RW*160
    float* sfin = red + RW * JD;                               // 160 (DSMEM)
    float* stot = sfin + JD;                                   // 160
    float* Vsm = stot + JD;                                    // 160
    float* scl = Vsm + JD;                                     // 16

    const int tid = threadIdx.x;
    const int warp = tid >> 5;
    const int lane = tid & 31;
    const int b = blockIdx.x >> 2;
    const unsigned int rank = blockIdx.x & 3;
    const bool act = (lane < 20);
    const int sl = act ? 4 * lane : 0;
    float2* red2 = (float2*)red;

    const __half2* gsrc = g_uhat + ((size_t)b * INC + rank * IQ) * NSLOT;

    // ---- stream u_hat quarter -> smem, accumulate pass-0 (c = 0.1) ----
    float2 a0 = make_float2(0.f, 0.f), a1 = a0, a2 = a0, a3 = a0;
    if (act) {
#pragma unroll 2
        for (int i = warp; i < IQ; i += RW) {
            uint4 u = *(const uint4*)(gsrc + (size_t)i * NSLOT + sl);
            *(uint4*)(Usm + (size_t)i * NSLOT + sl) = u;
            __half2 h0 = *(__half2*)&u.x, h1 = *(__half2*)&u.y;
            __half2 h2 = *(__half2*)&u.z, h3 = *(__half2*)&u.w;
            float2 f0 = __half22float2(h0), f1 = __half22float2(h1);
            float2 f2 = __half22float2(h2), f3 = __half22float2(h3);
            a0.x += f0.x; a0.y += f0.y; a1.x += f1.x; a1.y += f1.y;
            a2.x += f2.x; a2.y += f2.y; a3.x += f3.x; a3.y += f3.y;
        }
        red2[warp * 80 + sl + 0] = a0;
        red2[warp * 80 + sl + 1] = a1;
        red2[warp * 80 + sl + 2] = a2;
        red2[warp * 80 + sl + 3] = a3;
    }
    __syncthreads();
    if (tid < JD) {
        float s = 0.f;
#pragma unroll
        for (int w = 0; w < RW; w++) s += red[w * JD + tid];
        sfin[tid] = s;
    }
    __syncthreads();
    cluster_sync();
    if (tid < JD) {
        float s = sfin[tid];
#pragma unroll
        for (unsigned int r = 1; r < CSZ; r++)
            s += peer_f32(sfin + tid, rank ^ r);
        stot[tid] = 0.1f * s;
    }
    __syncthreads();
    if (tid < NC) {
        float sq = 0.f;
#pragma unroll
        for (int d = 0; d < DC; d++) {
            float v = stot[tid * DC + d];
            sq = fmaf(v, v, sq);
        }
        scl[tid] = sq / ((1.0f + sq) * sqrtf(sq + EPSQ));
    }
    __syncthreads();
    if (tid < JD) Vsm[tid] = scl[tid >> 4] * stot[tid];
    __syncthreads();
    cluster_sync();  // peers done reading sfin; Vsm ready

    // ---- passes 1,2 from smem ----
    for (int p = 1; p <= 2; p++) {
        const float2* V2 = (const float2*)Vsm;
        float2 v0 = V2[sl], v1 = V2[sl + 1], v2 = V2[sl + 2], v3 = V2[sl + 3];
        float2 s0 = make_float2(0.f, 0.f), s1 = s0, s2 = s0, s3 = s0;
#pragma unroll 2
        for (int i = warp; i < IQ; i += RW) {
            uint4 u = *(const uint4*)(Usm + (size_t)i * NSLOT + sl);
            __half2 h0 = *(__half2*)&u.x, h1 = *(__half2*)&u.y;
            __half2 h2 = *(__half2*)&u.z, h3 = *(__half2*)&u.w;
            float2 f0 = __half22float2(h0), f1 = __half22float2(h1);
            float2 f2 = __half22float2(h2), f3 = __half22float2(h3);

            float t = f0.x * v0.x + f0.y * v0.y;
            t = fmaf(f1.x, v1.x, t); t = fmaf(f1.y, v1.y, t);
            t = fmaf(f2.x, v2.x, t); t = fmaf(f2.y, v2.y, t);
            t = fmaf(f3.x, v3.x, t); t = fmaf(f3.y, v3.y, t);
            t += __shfl_xor_sync(0xffffffffu, t, 1);  // full dot, j = lane>>1

            // |t| < ~4 -> no max-subtraction needed
            float e = act ? __expf(t) : 0.f;
            float sv = e;
            sv += __shfl_xor_sync(0xffffffffu, sv, 2);
            sv += __shfl_xor_sync(0xffffffffu, sv, 4);
            sv += __shfl_xor_sync(0xffffffffu, sv, 8);
            sv += __shfl_xor_sync(0xffffffffu, sv, 16);  // = sum_j e_j exactly
            float c = e * __fdividef(1.f, sv);

            s0.x = fmaf(c, f0.x, s0.x); s0.y = fmaf(c, f0.y, s0.y);
            s1.x = fmaf(c, f1.x, s1.x); s1.y = fmaf(c, f1.y, s1.y);
            s2.x = fmaf(c, f2.x, s2.x); s2.y = fmaf(c, f2.y, s2.y);
            s3.x = fmaf(c, f3.x, s3.x); s3.y = fmaf(c, f3.y, s3.y);
        }
        if (act) {
            red2[warp * 80 + sl + 0] = s0;
            red2[warp * 80 + sl + 1] = s1;
            red2[warp * 80 + sl + 2] = s2;
            red2[warp * 80 + sl + 3] = s3;
        }
        __syncthreads();
        if (tid < JD) {
            float s = 0.f;
#pragma unroll
            for (int w = 0; w < RW; w++) s += red[w * JD + tid];
            sfin[tid] = s;
        }
        __syncthreads();
        cluster_sync();
        if (tid < JD) {
            float s = sfin[tid];
#pragma unroll
            for (unsigned int r = 1; r < CSZ; r++)
                s += peer_f32(sfin + tid, rank ^ r);
            stot[tid] = s;
        }
        __syncthreads();
        if (tid < NC) {
            float sq = 0.f;
#pragma unroll
            for (int d = 0; d < DC; d++) {
                float v = stot[tid * DC + d];
                sq = fmaf(v, v, sq);
            }
            scl[tid] = sq / ((1.0f + sq) * sqrtf(sq + EPSQ));
        }
        __syncthreads();
        if (p == 1) {
            if (tid < JD) Vsm[tid] += scl[tid >> 4] * stot[tid];
            __syncthreads();
        } else {
            if (rank == 0 && tid < JD)
                out[(size_t)b * JD + tid] = scl[tid >> 4] * stot[tid];
        }
        cluster_sync();  // sfin reuse / exit safety
    }
}

// ---------------------------------------------------------------------------
extern "C" void kernel_launch(void* const* d_in, const int* in_sizes, int n_in,
                              void* d_out, int out_size) {
    const float* inputs = (const float*)d_in[0];  // [512, 1152, 8]
    const float* W = (const float*)d_in[1];       // [10, 1152, 16, 8]
    float* out = (float*)d_out;                   // [512, 10, 16]

    uhat_kernel<<<INC, 256>>>(inputs, W);

    const int smem = IQ * NSLOT * 4 + (RW * JD + 3 * JD + 16) * 4;  // ~102 KB
    cudaFuncSetAttribute(route_kernel,
                         cudaFuncAttributeMaxDynamicSharedMemorySize, smem);
    route_kernel<<<BATCH * CSZ, 384, smem>>>(out);
}